// round 5
// baseline (speedup 1.0000x reference)
#include <cuda_runtime.h>
#include <cstdint>

// ---------------- problem sizes ----------------
// f1,f2: [16,256,256,60]  x1,x2: [16,256,3]
// Wp: [256,259] bp: [256]
// W0: [256,512] b0:[256]  W1: [256,256] b1:[256]
// Wa: [1,256] ba:[1]  Wr: [6,256] br:[6]
// out: confidence [16,60,60] (57600) then y [16,6,60,60] (345600)

#define NBv   16
#define CCv   256
#define NPv   256
#define NAv   60
#define NPIXv 3600
#define CONF_SZ (16*60*60)

// ---------------- device scratch (no cudaMalloc allowed) ----------------
__device__ float g_gbuf[2 * NBv * CCv * NAv];    // relu(max_p) pooled features, per cloud
__device__ float g_ubuf[2 * NBv * CCv * NAv];    // u1 (w=0, indexed by j), u2 (w=1, indexed by i)
__device__ float g_h1buf[NBv * NPIXv * CCv];     // h1, pixel-major [b][pix][o]  (59 MB)

// ---------------- f32x2 helpers ----------------
__device__ __forceinline__ unsigned long long pk2(float lo, float hi) {
    unsigned long long r;
    asm("mov.b64 %0, {%1, %2};" : "=l"(r) : "f"(lo), "f"(hi));
    return r;
}
__device__ __forceinline__ void upk2(float& lo, float& hi, unsigned long long v) {
    asm("mov.b64 {%0, %1}, %2;" : "=f"(lo), "=f"(hi) : "l"(v));
}
#define FMA2(acc, a, b) asm("fma.rn.f32x2 %0, %1, %2, %0;" : "+l"(acc) : "l"(a), "l"(b))

// ---------------- kernel 0: zero the max buffer ----------------
__global__ void kZero() {
    int i = blockIdx.x * blockDim.x + threadIdx.x;
    if (i < 2 * NBv * CCv * NAv) g_gbuf[i] = 0.0f;
}

// ---------------- kernel A: fused pointnet GEMM + max-pool ----------------
// grid: x = (pchunk<<1)|ot  (8 p-chunks x 2 o-tiles = 16), y = b (16), z = cloud (2)
// block: 256 threads. smem: ws[256][132] + fs[256][64] + wx0/wx1/wx2/bps[128]
#define KA_SMEM_FLOATS (33792 + 16384 + 512)
__global__ void __launch_bounds__(256)
kA(const float* __restrict__ f1, const float* __restrict__ f2,
   const float* __restrict__ x1, const float* __restrict__ x2,
   const float* __restrict__ Wp, const float* __restrict__ bp)
{
    extern __shared__ float sm[];
    float* ws  = sm;                 // [c*132 + o], 33792 floats
    float* fs  = sm + 33792;         // [c*64 + a], 16384 floats
    float* wx0 = sm + 50176;
    float* wx1 = sm + 50304;
    float* wx2 = sm + 50432;
    float* bps = sm + 50560;

    const int cloud = blockIdx.z;
    const float* __restrict__ f = cloud ? f2 : f1;
    const float* __restrict__ x = cloud ? x2 : x1;
    const int b   = blockIdx.y;
    const int ot  = blockIdx.x & 1;
    const int pch = blockIdx.x >> 1;
    const int ob  = ot << 7;
    const int tid = threadIdx.x;

    // stage W tile transposed: ws[c][o]
    for (int idx = tid; idx < 128 * 256; idx += 256) {
        int o = idx >> 8, c = idx & 255;
        ws[c * 132 + o] = Wp[(size_t)(ob + o) * 259 + c];
    }
    if (tid < 128) {
        const float* wr = Wp + (size_t)(ob + tid) * 259;
        wx0[tid] = wr[256]; wx1[tid] = wr[257]; wx2[tid] = wr[258];
        bps[tid] = bp[ob + tid];
    }
    __syncthreads();

    const int ty = tid >> 4, tx = tid & 15;

    float maxv[32];
#pragma unroll
    for (int r = 0; r < 32; ++r) maxv[r] = 0.0f;   // relu(max) built in via 0-init

    for (int pp = 0; pp < 32; ++pp) {
        const int p = (pch << 5) + pp;
        // load f slice [256 c][60 a] (pad to 64)
        for (int idx = tid; idx < 256 * 16; idx += 256) {
            int c = idx >> 4, a4 = idx & 15;
            float4 v = make_float4(0.f, 0.f, 0.f, 0.f);
            if (a4 < 15) {
                size_t off = ((size_t)((b * 256 + c) * 256 + p)) * 60 + (a4 << 2);
                v = *(const float4*)(f + off);
            }
            *(float4*)(fs + (c << 6) + (a4 << 2)) = v;
        }
        __syncthreads();

        const float xv0 = x[(b * 256 + p) * 3 + 0];
        const float xv1 = x[(b * 256 + p) * 3 + 1];
        const float xv2 = x[(b * 256 + p) * 3 + 2];

        unsigned long long acc[16];
#pragma unroll
        for (int m = 0; m < 4; ++m) {
            int o0 = (ty << 3) + (m << 1);
            float ta = bps[o0]     + wx0[o0]     * xv0 + wx1[o0]     * xv1 + wx2[o0]     * xv2;
            float tb = bps[o0 + 1] + wx0[o0 + 1] * xv0 + wx1[o0 + 1] * xv1 + wx2[o0 + 1] * xv2;
            unsigned long long t = pk2(ta, tb);
#pragma unroll
            for (int s = 0; s < 4; ++s) acc[m * 4 + s] = t;
        }

#pragma unroll 2
        for (int c = 0; c < 256; ++c) {
            const float* wrow = ws + c * 132 + (ty << 3);
            unsigned long long w0 = *(const unsigned long long*)(wrow);
            unsigned long long w1 = *(const unsigned long long*)(wrow + 2);
            unsigned long long w2 = *(const unsigned long long*)(wrow + 4);
            unsigned long long w3 = *(const unsigned long long*)(wrow + 6);
            float4 fv = *(const float4*)(fs + (c << 6) + (tx << 2));
            unsigned long long d0 = pk2(fv.x, fv.x);
            unsigned long long d1 = pk2(fv.y, fv.y);
            unsigned long long d2 = pk2(fv.z, fv.z);
            unsigned long long d3 = pk2(fv.w, fv.w);
            FMA2(acc[0],  w0, d0); FMA2(acc[1],  w0, d1); FMA2(acc[2],  w0, d2); FMA2(acc[3],  w0, d3);
            FMA2(acc[4],  w1, d0); FMA2(acc[5],  w1, d1); FMA2(acc[6],  w1, d2); FMA2(acc[7],  w1, d3);
            FMA2(acc[8],  w2, d0); FMA2(acc[9],  w2, d1); FMA2(acc[10], w2, d2); FMA2(acc[11], w2, d3);
            FMA2(acc[12], w3, d0); FMA2(acc[13], w3, d1); FMA2(acc[14], w3, d2); FMA2(acc[15], w3, d3);
        }

#pragma unroll
        for (int m = 0; m < 4; ++m) {
#pragma unroll
            for (int s = 0; s < 4; ++s) {
                float lo, hi;
                upk2(lo, hi, acc[m * 4 + s]);
                maxv[(2 * m)     * 4 + s] = fmaxf(maxv[(2 * m)     * 4 + s], lo);
                maxv[(2 * m + 1) * 4 + s] = fmaxf(maxv[(2 * m + 1) * 4 + s], hi);
            }
        }
        __syncthreads();
    }

    // commit block-local max (all values >= 0 -> int-ordered atomicMax is valid)
    float* gb = g_gbuf + (size_t)((cloud * 16 + b) * 256) * 60;
#pragma unroll
    for (int r = 0; r < 8; ++r) {
        int o = ob + (ty << 3) + r;
#pragma unroll
        for (int s = 0; s < 4; ++s) {
            int a = (tx << 2) + s;
            if (a < 60)
                atomicMax((int*)(gb + o * 60 + a), __float_as_int(maxv[r * 4 + s]));
        }
    }
}

// ---------------- kernel B1: u[w][b][o][j] = sum_c W0[o][w*256+c] * g[w][b][c][j] ----------------
// grid: x = w (2), y = b (16). 256 threads, thread = o.
#define KB1_SMEM_FLOATS (15360 + 2304)
__global__ void __launch_bounds__(256)
kB1(const float* __restrict__ W0)
{
    extern __shared__ float sm[];
    float* gs  = sm;          // [c*60 + j], 15360
    float* wsm = sm + 15360;  // [o*9 + k], 2304

    const int w = blockIdx.x, b = blockIdx.y;
    const int tid = threadIdx.x;

    const float* gsrc = g_gbuf + (size_t)((w * 16 + b) * 256) * 60;
    for (int idx = tid; idx < 15360; idx += 256) gs[idx] = gsrc[idx];

    float4 acc[15];
#pragma unroll
    for (int j4 = 0; j4 < 15; ++j4) acc[j4] = make_float4(0.f, 0.f, 0.f, 0.f);

    for (int cc = 0; cc < 256; cc += 8) {
        __syncthreads();  // gs ready (1st iter) / wsm readers done
        for (int idx = tid; idx < 2048; idx += 256) {
            int o = idx >> 3, k = idx & 7;
            wsm[o * 9 + k] = W0[(size_t)o * 512 + w * 256 + cc + k];
        }
        __syncthreads();
        float w8[8];
#pragma unroll
        for (int k = 0; k < 8; ++k) w8[k] = wsm[tid * 9 + k];
#pragma unroll
        for (int k = 0; k < 8; ++k) {
            const float4* gp = (const float4*)(gs + (cc + k) * 60);
#pragma unroll
            for (int j4 = 0; j4 < 15; ++j4) {
                float4 gv = gp[j4];
                acc[j4].x += w8[k] * gv.x;
                acc[j4].y += w8[k] * gv.y;
                acc[j4].z += w8[k] * gv.z;
                acc[j4].w += w8[k] * gv.w;
            }
        }
    }

    float* dst = g_ubuf + (size_t)((w * 16 + b) * 256 + tid) * 60;
#pragma unroll
    for (int j4 = 0; j4 < 15; ++j4) *(float4*)(dst + (j4 << 2)) = acc[j4];
}

// ---------------- kernel B2a: h1 = relu(W1 @ relu(u1+u2+b0) + b1) ----------------
// grid: x = pixel chunk (57 of 64 px), y = o-tile (2), z = b (16). 256 threads.
#define KB2A_SMEM_FLOATS (33792 + 16384 + 128 + 256)
__global__ void __launch_bounds__(256)
kB2a(const float* __restrict__ W1, const float* __restrict__ b0, const float* __restrict__ b1)
{
    extern __shared__ float sm[];
    float* ws  = sm;           // [c*132 + o]
    float* hs  = sm + 33792;   // [c*64 + q]
    float* b1s = sm + 50176;   // 128
    float* b0s = sm + 50304;   // 256

    const int pc = blockIdx.x;
    const int ot = blockIdx.y;
    const int b  = blockIdx.z;
    const int ob = ot << 7;
    const int tid = threadIdx.x;

    // stage W1 tile transposed (vectorized global reads; W1 rows are 1 KB aligned)
    for (int idx = tid; idx < 128 * 64; idx += 256) {
        int o = idx >> 6, c4 = idx & 63;
        float4 v = *(const float4*)(W1 + ((size_t)(ob + o) << 8) + (c4 << 2));
        int cb = c4 << 2;
        ws[(cb)     * 132 + o] = v.x;
        ws[(cb + 1) * 132 + o] = v.y;
        ws[(cb + 2) * 132 + o] = v.z;
        ws[(cb + 3) * 132 + o] = v.w;
    }
    if (tid < 128) b1s[tid] = b1[ob + tid];
    if (tid < 256) b0s[tid] = b0[tid];
    __syncthreads();

    // build h0 tile in smem: hs[c][q] = relu(u1[b,c,j] + u2[b,c,i] + b0[c])
    const float* u1 = g_ubuf + (size_t)(b * 256) * 60;                 // w=0, index j
    const float* u2 = g_ubuf + (size_t)((16 + b) * 256) * 60;          // w=1, index i
    for (int idx = tid; idx < 256 * 64; idx += 256) {
        int c = idx >> 6, q = idx & 63;
        int pix = (pc << 6) + q;
        float v = 0.f;
        if (pix < NPIXv) {
            int i = pix / 60;
            int j = pix - i * 60;
            v = fmaxf(u1[c * 60 + j] + u2[c * 60 + i] + b0s[c], 0.f);
        }
        hs[(c << 6) + q] = v;
    }
    __syncthreads();

    const int ty = tid >> 4, tx = tid & 15;
    unsigned long long acc[16];
    const unsigned long long z = pk2(0.f, 0.f);
#pragma unroll
    for (int t = 0; t < 16; ++t) acc[t] = z;

#pragma unroll 2
    for (int c = 0; c < 256; ++c) {
        const float* wrow = ws + c * 132 + (ty << 3);
        unsigned long long w0 = *(const unsigned long long*)(wrow);
        unsigned long long w1 = *(const unsigned long long*)(wrow + 2);
        unsigned long long w2 = *(const unsigned long long*)(wrow + 4);
        unsigned long long w3 = *(const unsigned long long*)(wrow + 6);
        float4 fv = *(const float4*)(hs + (c << 6) + (tx << 2));
        unsigned long long d0 = pk2(fv.x, fv.x);
        unsigned long long d1 = pk2(fv.y, fv.y);
        unsigned long long d2 = pk2(fv.z, fv.z);
        unsigned long long d3 = pk2(fv.w, fv.w);
        FMA2(acc[0],  w0, d0); FMA2(acc[1],  w0, d1); FMA2(acc[2],  w0, d2); FMA2(acc[3],  w0, d3);
        FMA2(acc[4],  w1, d0); FMA2(acc[5],  w1, d1); FMA2(acc[6],  w1, d2); FMA2(acc[7],  w1, d3);
        FMA2(acc[8],  w2, d0); FMA2(acc[9],  w2, d1); FMA2(acc[10], w2, d2); FMA2(acc[11], w2, d3);
        FMA2(acc[12], w3, d0); FMA2(acc[13], w3, d1); FMA2(acc[14], w3, d2); FMA2(acc[15], w3, d3);
    }

    // epilogue: bias + relu, store pixel-major h1[b][pix][o]
#pragma unroll
    for (int s = 0; s < 4; ++s) {
        int pix = (pc << 6) + (tx << 2) + s;
        if (pix < NPIXv) {
            float v[8];
#pragma unroll
            for (int m = 0; m < 4; ++m) upk2(v[2 * m], v[2 * m + 1], acc[m * 4 + s]);
#pragma unroll
            for (int r = 0; r < 8; ++r) v[r] = fmaxf(v[r] + b1s[(ty << 3) + r], 0.f);
            float* dst = g_h1buf + ((size_t)(b * NPIXv + pix) << 8) + ob + (ty << 3);
            *(float4*)(dst)     = make_float4(v[0], v[1], v[2], v[3]);
            *(float4*)(dst + 4) = make_float4(v[4], v[5], v[6], v[7]);
        }
    }
}

// ---------------- kernel B2b: heads + softmax over i ----------------
// grid: x = j (60), y = b (16). 256 threads (8 warps).
__global__ void __launch_bounds__(256)
kB2b(const float* __restrict__ Wa, const float* __restrict__ ba,
     const float* __restrict__ Wr, const float* __restrict__ br,
     float* __restrict__ out)
{
    __shared__ float attnS[64];
    __shared__ float was[256];
    __shared__ float wrs[6 * 256];

    const int j = blockIdx.x, b = blockIdx.y;
    const int tid = threadIdx.x;
    for (int idx = tid; idx < 256; idx += 256)  was[idx] = Wa[idx];
    for (int idx = tid; idx < 1536; idx += 256) wrs[idx] = Wr[idx];
    __syncthreads();

    const int wp = tid >> 5, l = tid & 31;
    float* yout = out + CONF_SZ;

    for (int i = wp; i < 60; i += 8) {
        const float* hp = g_h1buf + ((size_t)(b * NPIXv + i * 60 + j) << 8);
        float sA = 0.f, s0 = 0.f, s1 = 0.f, s2 = 0.f, s3 = 0.f, s4 = 0.f, s5 = 0.f;
#pragma unroll
        for (int k = 0; k < 8; ++k) {
            int o = l + (k << 5);
            float h = hp[o];
            sA += h * was[o];
            s0 += h * wrs[o];        s1 += h * wrs[256 + o];  s2 += h * wrs[512 + o];
            s3 += h * wrs[768 + o];  s4 += h * wrs[1024 + o]; s5 += h * wrs[1280 + o];
        }
#pragma unroll
        for (int off = 16; off; off >>= 1) {
            sA += __shfl_xor_sync(0xffffffffu, sA, off);
            s0 += __shfl_xor_sync(0xffffffffu, s0, off);
            s1 += __shfl_xor_sync(0xffffffffu, s1, off);
            s2 += __shfl_xor_sync(0xffffffffu, s2, off);
            s3 += __shfl_xor_sync(0xffffffffu, s3, off);
            s4 += __shfl_xor_sync(0xffffffffu, s4, off);
            s5 += __shfl_xor_sync(0xffffffffu, s5, off);
        }
        if (l == 0) {
            attnS[i] = sA + ba[0];
            yout[((b * 6 + 0) * 60 + i) * 60 + j] = s0 + br[0];
            yout[((b * 6 + 1) * 60 + i) * 60 + j] = s1 + br[1];
            yout[((b * 6 + 2) * 60 + i) * 60 + j] = s2 + br[2];
            yout[((b * 6 + 3) * 60 + i) * 60 + j] = s3 + br[3];
            yout[((b * 6 + 4) * 60 + i) * 60 + j] = s4 + br[4];
            yout[((b * 6 + 5) * 60 + i) * 60 + j] = s5 + br[5];
        }
    }
    __syncthreads();

    if (tid < 32) {
        float v0 = (tid      < 60) ? attnS[tid]      : -1e30f;
        float v1 = (tid + 32 < 60) ? attnS[tid + 32] : -1e30f;
        float m = fmaxf(v0, v1);
#pragma unroll
        for (int off = 16; off; off >>= 1) m = fmaxf(m, __shfl_xor_sync(0xffffffffu, m, off));
        float e0 = (tid      < 60) ? expf(v0 - m) : 0.f;
        float e1 = (tid + 32 < 60) ? expf(v1 - m) : 0.f;
        float s = e0 + e1;
#pragma unroll
        for (int off = 16; off; off >>= 1) s += __shfl_xor_sync(0xffffffffu, s, off);
        float inv = 1.f / s;
        if (tid < 60)      out[(b * 60 + tid)      * 60 + j] = e0 * inv;
        if (tid + 32 < 60) out[(b * 60 + tid + 32) * 60 + j] = e1 * inv;
    }
}

// ---------------- launch ----------------
extern "C" void kernel_launch(void* const* d_in, const int* in_sizes, int n_in,
                              void* d_out, int out_size)
{
    const float* f1 = (const float*)d_in[0];
    const float* f2 = (const float*)d_in[1];
    const float* x1 = (const float*)d_in[2];
    const float* x2 = (const float*)d_in[3];
    const float* Wp = (const float*)d_in[4];
    const float* bp = (const float*)d_in[5];
    const float* W0 = (const float*)d_in[6];
    const float* b0 = (const float*)d_in[7];
    const float* W1 = (const float*)d_in[8];
    const float* b1 = (const float*)d_in[9];
    const float* Wa = (const float*)d_in[10];
    const float* ba = (const float*)d_in[11];
    const float* Wr = (const float*)d_in[12];
    const float* br = (const float*)d_in[13];
    float* out = (float*)d_out;

    cudaFuncSetAttribute(kA,   cudaFuncAttributeMaxDynamicSharedMemorySize, KA_SMEM_FLOATS * 4);
    cudaFuncSetAttribute(kB1,  cudaFuncAttributeMaxDynamicSharedMemorySize, KB1_SMEM_FLOATS * 4);
    cudaFuncSetAttribute(kB2a, cudaFuncAttributeMaxDynamicSharedMemorySize, KB2A_SMEM_FLOATS * 4);

    kZero<<<(2 * NBv * CCv * NAv + 255) / 256, 256>>>();
    kA<<<dim3(16, 16, 2), 256, KA_SMEM_FLOATS * 4>>>(f1, f2, x1, x2, Wp, bp);
    kB1<<<dim3(2, 16), 256, KB1_SMEM_FLOATS * 4>>>(W0);
    kB2a<<<dim3(57, 2, 16), 256, KB2A_SMEM_FLOATS * 4>>>(W1, b0, b1);
    kB2b<<<dim3(60, 16), 256>>>(Wa, ba, Wr, br, out);
}

// round 8
// speedup vs baseline: 1.0238x; 1.0238x over previous
#include <cuda_runtime.h>
#include <cstdint>

// ---------------- problem sizes ----------------
// f1,f2: [16,256,256,60]  x1,x2: [16,256,3]
// Wp: [256,259] bp: [256]
// W0: [256,512] b0:[256]  W1: [256,256] b1:[256]
// Wa: [1,256] ba:[1]  Wr: [6,256] br:[6]
// out: confidence [16,60,60] (57600) then y [16,6,60,60] (345600)

#define NBv   16
#define CCv   256
#define NPv   256
#define NAv   60
#define NPIXv 3600
#define CONF_SZ (16*60*60)

// ---------------- device scratch ----------------
__device__ float g_gbuf[2 * NBv * CCv * NAv];
__device__ float g_ubuf[2 * NBv * CCv * NAv];
__device__ float g_h1buf[NBv * NPIXv * CCv];   // h1 pixel-major [b][pix][o]

// ---------------- f32x2 helpers ----------------
__device__ __forceinline__ unsigned long long pk2(float lo, float hi) {
    unsigned long long r;
    asm("mov.b64 %0, {%1, %2};" : "=l"(r) : "f"(lo), "f"(hi));
    return r;
}
__device__ __forceinline__ void upk2(float& lo, float& hi, unsigned long long v) {
    asm("mov.b64 {%0, %1}, %2;" : "=f"(lo), "=f"(hi) : "l"(v));
}
#define FMA2(acc, a, b) asm("fma.rn.f32x2 %0, %1, %2, %0;" : "+l"(acc) : "l"(a), "l"(b))

// ---------------- cp.async helpers ----------------
__device__ __forceinline__ void cp_async16(uint32_t dst, const void* src) {
    asm volatile("cp.async.ca.shared.global [%0], [%1], 16;\n" :: "r"(dst), "l"(src));
}
__device__ __forceinline__ void cp_commit() { asm volatile("cp.async.commit_group;\n" ::: "memory"); }
__device__ __forceinline__ void cp_wait1()  { asm volatile("cp.async.wait_group 1;\n" ::: "memory"); }
__device__ __forceinline__ void cp_wait0()  { asm volatile("cp.async.wait_group 0;\n" ::: "memory"); }

// ---------------- kernel 0: zero the max buffer ----------------
__global__ void kZero() {
    int i = blockIdx.x * blockDim.x + threadIdx.x;
    if (i < 2 * NBv * CCv * NAv) g_gbuf[i] = 0.0f;
}

// =====================================================================
// kernel A: fused pointnet GEMM + max-pool. 512 threads, cp.async pipe.
// grid: x = (pchunk<<1)|ot (16), y = b (16), z = cloud (2)
// smem: ws[256][136] | fs 2x[128][64] | wx0/wx1/wx2/bps[128]
// =====================================================================
#define KA_WS_F    (256 * 136)              // 34816
#define KA_FS_F    (2 * 128 * 64)           // 16384
#define KA_AUX_OFF (KA_WS_F + KA_FS_F)      // 51200
#define KA_SMEM_FLOATS (KA_AUX_OFF + 512)   // 51712 floats = 206848 B

__global__ void __launch_bounds__(512)
kA(const float* __restrict__ f1, const float* __restrict__ f2,
   const float* __restrict__ x1, const float* __restrict__ x2,
   const float* __restrict__ Wp, const float* __restrict__ bp)
{
    extern __shared__ float sm[];
    float* ws  = sm;                     // [c*136 + o]
    float* fs  = sm + KA_WS_F;           // 2 buffers of 8192
    float* wx0 = sm + KA_AUX_OFF;
    float* wx1 = sm + KA_AUX_OFF + 128;
    float* wx2 = sm + KA_AUX_OFF + 256;
    float* bps = sm + KA_AUX_OFF + 384;

    const int cloud = blockIdx.z;
    const float* __restrict__ f = cloud ? f2 : f1;
    const float* __restrict__ x = cloud ? x2 : x1;
    const int b   = blockIdx.y;
    const int ot  = blockIdx.x & 1;
    const int pch = blockIdx.x >> 1;
    const int ob  = ot << 7;
    const int tid = threadIdx.x;

    const uint32_t fs_u32 = (uint32_t)__cvta_generic_to_shared(fs);

    // stage W tile transposed: ws[c][o] (rows of Wp are contiguous -> coalesced)
    for (int idx = tid; idx < 128 * 256; idx += 512) {
        int o = idx >> 8, c = idx & 255;
        ws[c * 136 + o] = Wp[(size_t)(ob + o) * 259 + c];
    }
    if (tid < 128) {
        const float* wr = Wp + (size_t)(ob + tid) * 259;
        wx0[tid] = wr[256]; wx1[tid] = wr[257]; wx2[tid] = wr[258];
        bps[tid] = bp[ob + tid];
    }
    // zero the a=60..63 tail of both fs buffers (never written by cp.async)
    for (int idx = tid; idx < 1024; idx += 512) {
        int bb = idx >> 9, c = (idx >> 2) & 127, a = 60 + (idx & 3);
        fs[bb * 8192 + (c << 6) + a] = 0.f;
    }
    __syncthreads();

    const int ty = tid >> 4, tx = tid & 15;   // ty: o-quad (0..31), tx: a-quad (0..15)

    // per-thread copies of bias / xyz weights for this thread's 4 o's
    float bpr[4], wr0[4], wr1[4], wr2[4];
#pragma unroll
    for (int r = 0; r < 4; ++r) {
        int o = (ty << 2) + r;
        bpr[r] = bps[o]; wr0[r] = wx0[o]; wr1[r] = wx1[o]; wr2[r] = wx2[o];
    }

    float maxv[16];
#pragma unroll
    for (int r = 0; r < 16; ++r) maxv[r] = 0.0f;   // relu(max) via 0-init

    // prefetch chunk 0 (t=0): p = pch*32, c-range [0,128)
    {
        const int p0 = pch << 5;
        for (int idx = tid; idx < 2048; idx += 512) {
            int c = idx >> 4, a4 = idx & 15;
            if (a4 < 15) {
                const float* src = f + ((size_t)((b * 256 + c) * 256 + p0)) * 60 + (a4 << 2);
                cp_async16(fs_u32 + (uint32_t)((c << 6) + (a4 << 2)) * 4u, src);
            }
        }
        cp_commit();
    }

    unsigned long long acc[8];

    for (int t = 0; t < 64; ++t) {
        // prefetch chunk t+1 into buffer (t+1)&1
        if (t + 1 < 64) {
            const int pn = (pch << 5) + ((t + 1) >> 1);
            const int cb = ((t + 1) & 1) << 7;
            const uint32_t dstb = fs_u32 + (uint32_t)(((t + 1) & 1) * 8192) * 4u;
            for (int idx = tid; idx < 2048; idx += 512) {
                int c = idx >> 4, a4 = idx & 15;
                if (a4 < 15) {
                    const float* src = f + ((size_t)((b * 256 + cb + c) * 256 + pn)) * 60 + (a4 << 2);
                    cp_async16(dstb + (uint32_t)((c << 6) + (a4 << 2)) * 4u, src);
                }
            }
            cp_commit();
            cp_wait1();   // ensure chunk t's data has landed
        } else {
            cp_wait0();   // final iteration: drain everything
        }
        __syncthreads();

        const int p    = (pch << 5) + (t >> 1);
        const int half = t & 1;

        if (half == 0) {
            const float* xp = x + (b * 256 + p) * 3;
            const float xv0 = xp[0], xv1 = xp[1], xv2 = xp[2];
            float tv[4];
#pragma unroll
            for (int r = 0; r < 4; ++r)
                tv[r] = bpr[r] + wr0[r] * xv0 + wr1[r] * xv1 + wr2[r] * xv2;
            unsigned long long i0 = pk2(tv[0], tv[1]);
            unsigned long long i1 = pk2(tv[2], tv[3]);
#pragma unroll
            for (int s = 0; s < 4; ++s) { acc[s] = i0; acc[4 + s] = i1; }
        }

        const float* wp_s = ws + (size_t)(half << 7) * 136 + (ty << 2);
        const float* fp_s = fs + ((t & 1) * 8192) + (tx << 2);
#pragma unroll 4
        for (int c = 0; c < 128; ++c) {
            ulonglong2 wv = *(const ulonglong2*)(wp_s + c * 136);
            float4 fv = *(const float4*)(fp_s + (c << 6));
            unsigned long long d0 = pk2(fv.x, fv.x);
            unsigned long long d1 = pk2(fv.y, fv.y);
            unsigned long long d2 = pk2(fv.z, fv.z);
            unsigned long long d3 = pk2(fv.w, fv.w);
            FMA2(acc[0], wv.x, d0); FMA2(acc[1], wv.x, d1);
            FMA2(acc[2], wv.x, d2); FMA2(acc[3], wv.x, d3);
            FMA2(acc[4], wv.y, d0); FMA2(acc[5], wv.y, d1);
            FMA2(acc[6], wv.y, d2); FMA2(acc[7], wv.y, d3);
        }

        if (half == 1) {
#pragma unroll
            for (int s = 0; s < 4; ++s) {
                float lo, hi;
                upk2(lo, hi, acc[s]);
                maxv[0 * 4 + s] = fmaxf(maxv[0 * 4 + s], lo);
                maxv[1 * 4 + s] = fmaxf(maxv[1 * 4 + s], hi);
                upk2(lo, hi, acc[4 + s]);
                maxv[2 * 4 + s] = fmaxf(maxv[2 * 4 + s], lo);
                maxv[3 * 4 + s] = fmaxf(maxv[3 * 4 + s], hi);
            }
        }
        __syncthreads();   // buffer (t&1) may be overwritten by next prefetch
    }

    // commit block-local max (values >= 0 -> int-ordered atomicMax valid)
    float* gb = g_gbuf + (size_t)((cloud * 16 + b) * 256) * 60;
#pragma unroll
    for (int r = 0; r < 4; ++r) {
        int o = ob + (ty << 2) + r;
#pragma unroll
        for (int s = 0; s < 4; ++s) {
            int a = (tx << 2) + s;
            if (a < 60)
                atomicMax((int*)(gb + o * 60 + a), __float_as_int(maxv[r * 4 + s]));
        }
    }
}

// ---------------- kernel B1: u[w][b][o][j] = sum_c W0[o][w*256+c] * g[w][b][c][j]
// grid: x = w (2), y = b (16). 256 threads, thread = o.
#define KB1_SMEM_FLOATS (15360 + 2304)
__global__ void __launch_bounds__(256)
kB1(const float* __restrict__ W0)
{
    extern __shared__ float sm[];
    float* gs  = sm;          // [c*60 + j]
    float* wsm = sm + 15360;  // [o*9 + k]

    const int w = blockIdx.x, b = blockIdx.y;
    const int tid = threadIdx.x;

    const float* gsrc = g_gbuf + (size_t)((w * 16 + b) * 256) * 60;
    for (int idx = tid; idx < 15360; idx += 256) gs[idx] = gsrc[idx];

    float4 acc[15];
#pragma unroll
    for (int j4 = 0; j4 < 15; ++j4) acc[j4] = make_float4(0.f, 0.f, 0.f, 0.f);

    for (int cc = 0; cc < 256; cc += 8) {
        __syncthreads();
        for (int idx = tid; idx < 2048; idx += 256) {
            int o = idx >> 3, k = idx & 7;
            wsm[o * 9 + k] = W0[(size_t)o * 512 + w * 256 + cc + k];
        }
        __syncthreads();
        float w8[8];
#pragma unroll
        for (int k = 0; k < 8; ++k) w8[k] = wsm[tid * 9 + k];
#pragma unroll
        for (int k = 0; k < 8; ++k) {
            const float4* gp = (const float4*)(gs + (cc + k) * 60);
#pragma unroll
            for (int j4 = 0; j4 < 15; ++j4) {
                float4 gv = gp[j4];
                acc[j4].x += w8[k] * gv.x;
                acc[j4].y += w8[k] * gv.y;
                acc[j4].z += w8[k] * gv.z;
                acc[j4].w += w8[k] * gv.w;
            }
        }
    }

    float* dst = g_ubuf + (size_t)((w * 16 + b) * 256 + tid) * 60;
#pragma unroll
    for (int j4 = 0; j4 < 15; ++j4) *(float4*)(dst + (j4 << 2)) = acc[j4];
}

// =====================================================================
// kernel B2a: h1 = relu(W1 @ relu(u1+u2+b0) + b1). 512 threads.
// grid: x = pixel chunk (57), y = o-tile (2), z = b (16).
// smem: ws[256][136] | hs[256][64] | b1s[128] | b0s[256]
// =====================================================================
#define KB2A_HS_OFF  KA_WS_F                    // 34816
#define KB2A_B1_OFF  (KB2A_HS_OFF + 16384)      // 51200
#define KB2A_B0_OFF  (KB2A_B1_OFF + 128)        // 51328
#define KB2A_SMEM_FLOATS (KB2A_B0_OFF + 256)    // 51584 floats = 206336 B

__global__ void __launch_bounds__(512)
kB2a(const float* __restrict__ W1, const float* __restrict__ b0, const float* __restrict__ b1)
{
    extern __shared__ float sm[];
    float* ws  = sm;                   // [c*136 + o]
    float* hs  = sm + KB2A_HS_OFF;     // [c*64 + q]
    float* b1s = sm + KB2A_B1_OFF;
    float* b0s = sm + KB2A_B0_OFF;

    const int pc = blockIdx.x;
    const int ot = blockIdx.y;
    const int b  = blockIdx.z;
    const int ob = ot << 7;
    const int tid = threadIdx.x;

    // stage W1 tile transposed (vectorized reads; W1 rows 1KB-aligned)
    for (int idx = tid; idx < 128 * 64; idx += 512) {
        int o = idx >> 6, c4 = idx & 63;
        float4 v = *(const float4*)(W1 + ((size_t)(ob + o) << 8) + (c4 << 2));
        int cb = c4 << 2;
        ws[(cb)     * 136 + o] = v.x;
        ws[(cb + 1) * 136 + o] = v.y;
        ws[(cb + 2) * 136 + o] = v.z;
        ws[(cb + 3) * 136 + o] = v.w;
    }
    if (tid < 128) b1s[tid] = b1[ob + tid];
    if (tid < 256) b0s[tid] = b0[tid];
    __syncthreads();

    // build h0 tile: hs[c][q] = relu(u1[b,c,j] + u2[b,c,i] + b0[c])
    const float* u1 = g_ubuf + (size_t)(b * 256) * 60;
    const float* u2 = g_ubuf + (size_t)((16 + b) * 256) * 60;
    for (int idx = tid; idx < 256 * 64; idx += 512) {
        int c = idx >> 6, q = idx & 63;
        int pix = (pc << 6) + q;
        float v = 0.f;
        if (pix < NPIXv) {
            int i = pix / 60;
            int j = pix - i * 60;
            v = fmaxf(u1[c * 60 + j] + u2[c * 60 + i] + b0s[c], 0.f);
        }
        hs[(c << 6) + q] = v;
    }
    __syncthreads();

    const int ty = tid >> 4, tx = tid & 15;   // ty: o-quad, tx: pix-quad
    unsigned long long acc[8];
    const unsigned long long z = pk2(0.f, 0.f);
#pragma unroll
    for (int t = 0; t < 8; ++t) acc[t] = z;

    const float* wp_s = ws + (ty << 2);
    const float* fp_s = hs + (tx << 2);
#pragma unroll 4
    for (int c = 0; c < 256; ++c) {
        ulonglong2 wv = *(const ulonglong2*)(wp_s + c * 136);
        float4 fv = *(const float4*)(fp_s + (c << 6));
        unsigned long long d0 = pk2(fv.x, fv.x);
        unsigned long long d1 = pk2(fv.y, fv.y);
        unsigned long long d2 = pk2(fv.z, fv.z);
        unsigned long long d3 = pk2(fv.w, fv.w);
        FMA2(acc[0], wv.x, d0); FMA2(acc[1], wv.x, d1);
        FMA2(acc[2], wv.x, d2); FMA2(acc[3], wv.x, d3);
        FMA2(acc[4], wv.y, d0); FMA2(acc[5], wv.y, d1);
        FMA2(acc[6], wv.y, d2); FMA2(acc[7], wv.y, d3);
    }

    // epilogue: bias + relu, store pixel-major h1[b][pix][o] (float4 per thread)
#pragma unroll
    for (int s = 0; s < 4; ++s) {
        int pix = (pc << 6) + (tx << 2) + s;
        if (pix < NPIXv) {
            float v0, v1, v2, v3;
            upk2(v0, v1, acc[s]);
            upk2(v2, v3, acc[4 + s]);
            int o0 = (ty << 2);
            v0 = fmaxf(v0 + b1s[o0],     0.f);
            v1 = fmaxf(v1 + b1s[o0 + 1], 0.f);
            v2 = fmaxf(v2 + b1s[o0 + 2], 0.f);
            v3 = fmaxf(v3 + b1s[o0 + 3], 0.f);
            float* dst = g_h1buf + ((size_t)(b * NPIXv + pix) << 8) + ob + o0;
            *(float4*)dst = make_float4(v0, v1, v2, v3);
        }
    }
}

// ---------------- kernel B2b: heads + softmax over i ----------------
// grid: x = j (60), y = b (16). 256 threads (8 warps).
__global__ void __launch_bounds__(256)
kB2b(const float* __restrict__ Wa, const float* __restrict__ ba,
     const float* __restrict__ Wr, const float* __restrict__ br,
     float* __restrict__ out)
{
    __shared__ float attnS[64];
    __shared__ float was[256];
    __shared__ float wrs[6 * 256];

    const int j = blockIdx.x, b = blockIdx.y;
    const int tid = threadIdx.x;
    for (int idx = tid; idx < 256; idx += 256)  was[idx] = Wa[idx];
    for (int idx = tid; idx < 1536; idx += 256) wrs[idx] = Wr[idx];
    __syncthreads();

    const int wp = tid >> 5, l = tid & 31;
    float* yout = out + CONF_SZ;

    for (int i = wp; i < 60; i += 8) {
        const float* hp = g_h1buf + ((size_t)(b * NPIXv + i * 60 + j) << 8);
        float sA = 0.f, s0 = 0.f, s1 = 0.f, s2 = 0.f, s3 = 0.f, s4 = 0.f, s5 = 0.f;
#pragma unroll
        for (int k = 0; k < 8; ++k) {
            int o = l + (k << 5);
            float h = hp[o];
            sA += h * was[o];
            s0 += h * wrs[o];        s1 += h * wrs[256 + o];  s2 += h * wrs[512 + o];
            s3 += h * wrs[768 + o];  s4 += h * wrs[1024 + o]; s5 += h * wrs[1280 + o];
        }
#pragma unroll
        for (int off = 16; off; off >>= 1) {
            sA += __shfl_xor_sync(0xffffffffu, sA, off);
            s0 += __shfl_xor_sync(0xffffffffu, s0, off);
            s1 += __shfl_xor_sync(0xffffffffu, s1, off);
            s2 += __shfl_xor_sync(0xffffffffu, s2, off);
            s3 += __shfl_xor_sync(0xffffffffu, s3, off);
            s4 += __shfl_xor_sync(0xffffffffu, s4, off);
            s5 += __shfl_xor_sync(0xffffffffu, s5, off);
        }
        if (l == 0) {
            attnS[i] = sA + ba[0];
            yout[((b * 6 + 0) * 60 + i) * 60 + j] = s0 + br[0];
            yout[((b * 6 + 1) * 60 + i) * 60 + j] = s1 + br[1];
            yout[((b * 6 + 2) * 60 + i) * 60 + j] = s2 + br[2];
            yout[((b * 6 + 3) * 60 + i) * 60 + j] = s3 + br[3];
            yout[((b * 6 + 4) * 60 + i) * 60 + j] = s4 + br[4];
            yout[((b * 6 + 5) * 60 + i) * 60 + j] = s5 + br[5];
        }
    }
    __syncthreads();

    if (tid < 32) {
        float v0 = (tid      < 60) ? attnS[tid]      : -1e30f;
        float v1 = (tid + 32 < 60) ? attnS[tid + 32] : -1e30f;
        float m = fmaxf(v0, v1);
#pragma unroll
        for (int off = 16; off; off >>= 1) m = fmaxf(m, __shfl_xor_sync(0xffffffffu, m, off));
        float e0 = (tid      < 60) ? expf(v0 - m) : 0.f;
        float e1 = (tid + 32 < 60) ? expf(v1 - m) : 0.f;
        float s = e0 + e1;
#pragma unroll
        for (int off = 16; off; off >>= 1) s += __shfl_xor_sync(0xffffffffu, s, off);
        float inv = 1.f / s;
        if (tid < 60)      out[(b * 60 + tid)      * 60 + j] = e0 * inv;
        if (tid + 32 < 60) out[(b * 60 + tid + 32) * 60 + j] = e1 * inv;
    }
}

// ---------------- launch ----------------
extern "C" void kernel_launch(void* const* d_in, const int* in_sizes, int n_in,
                              void* d_out, int out_size)
{
    const float* f1 = (const float*)d_in[0];
    const float* f2 = (const float*)d_in[1];
    const float* x1 = (const float*)d_in[2];
    const float* x2 = (const float*)d_in[3];
    const float* Wp = (const float*)d_in[4];
    const float* bp = (const float*)d_in[5];
    const float* W0 = (const float*)d_in[6];
    const float* b0 = (const float*)d_in[7];
    const float* W1 = (const float*)d_in[8];
    const float* b1 = (const float*)d_in[9];
    const float* Wa = (const float*)d_in[10];
    const float* ba = (const float*)d_in[11];
    const float* Wr = (const float*)d_in[12];
    const float* br = (const float*)d_in[13];
    float* out = (float*)d_out;

    cudaFuncSetAttribute(kA,   cudaFuncAttributeMaxDynamicSharedMemorySize, KA_SMEM_FLOATS * 4);
    cudaFuncSetAttribute(kB1,  cudaFuncAttributeMaxDynamicSharedMemorySize, KB1_SMEM_FLOATS * 4);
    cudaFuncSetAttribute(kB2a, cudaFuncAttributeMaxDynamicSharedMemorySize, KB2A_SMEM_FLOATS * 4);

    kZero<<<(2 * NBv * CCv * NAv + 255) / 256, 256>>>();
    kA<<<dim3(16, 16, 2), 512, KA_SMEM_FLOATS * 4>>>(f1, f2, x1, x2, Wp, bp);
    kB1<<<dim3(2, 16), 256, KB1_SMEM_FLOATS * 4>>>(W0);
    kB2a<<<dim3(57, 2, 16), 512, KB2A_SMEM_FLOATS * 4>>>(W1, b0, b1);
    kB2b<<<dim3(60, 16), 256>>>(Wa, ba, Wr, br, out);
}